// round 3
// baseline (speedup 1.0000x reference)
#include <cuda_runtime.h>
#include <cuda_bf16.h>
#include <cstdint>
#include <cstddef>

// ---------------- problem dims (fixed for this problem) ----------------
#define DIMD 1024
#define HID  4096
#define MTOK 16384            // 4*4096 tokens
#define K1   2112             // 2*1024 (hi|lo) + 64 (adapter 16 + pad 48)
#define K2   8192             // 2*4096 (hi|lo)

// ---------------- device scratch (no cudaMalloc allowed) ----------------
__device__ __align__(1024) __nv_bfloat16 g_A1[(size_t)MTOK * K1];  // [x_hi | x_lo | t2 | 0]
__device__ __align__(1024) __nv_bfloat16 g_B1[(size_t)HID  * K1];  // [tern | tern | g*u/s | 0]
__device__ __align__(1024) __nv_bfloat16 g_R [(size_t)MTOK * K2];  // [rr_hi | rr_lo]
__device__ __align__(1024) __nv_bfloat16 g_B2[(size_t)DIMD * K2];  // [tern | tern]
__device__ float g_scale_fc[HID];
__device__ float g_scale_pj[DIMD];
__device__ float g_W[16 * DIMD];   // fast_b @ v

// ---------------- helpers ----------------
__device__ __forceinline__ uint32_t smem_to_u32(const void* p) {
    uint32_t a;
    asm("{ .reg .u64 t; cvta.to.shared.u64 t, %1; cvt.u32.u64 %0, t; }" : "=r"(a) : "l"(p));
    return a;
}
#define SW128(o) ((o) ^ (((o) >> 3) & 0x70))

__device__ __forceinline__ void cp_async16(uint32_t s, const void* g) {
    asm volatile("cp.async.cg.shared.global [%0], [%1], 16;" :: "r"(s), "l"(g) : "memory");
}
__device__ __forceinline__ void cp_commit() {
    asm volatile("cp.async.commit_group;" ::: "memory");
}
template <int N>
__device__ __forceinline__ void cp_wait() {
    asm volatile("cp.async.wait_group %0;" :: "n"(N) : "memory");
}

__device__ __forceinline__ void ldm_x4(uint32_t addr, uint32_t* r) {
    asm volatile("ldmatrix.sync.aligned.m8n8.x4.shared.b16 {%0,%1,%2,%3}, [%4];"
        : "=r"(r[0]), "=r"(r[1]), "=r"(r[2]), "=r"(r[3]) : "r"(addr));
}
__device__ __forceinline__ void mma16816(float* c, const uint32_t* a, uint32_t b0, uint32_t b1) {
    asm volatile("mma.sync.aligned.m16n8k16.row.col.f32.bf16.bf16.f32 "
        "{%0,%1,%2,%3}, {%4,%5,%6,%7}, {%8,%9}, {%0,%1,%2,%3};"
        : "+f"(c[0]), "+f"(c[1]), "+f"(c[2]), "+f"(c[3])
        : "r"(a[0]), "r"(a[1]), "r"(a[2]), "r"(a[3]), "r"(b0), "r"(b1));
}

// ============================================================================
// prep kernels
// ============================================================================

// per-output-row abs-mean scale -> ternary pack (duplicated for hi|lo halves).
// For w_fc also append gate*u/scale columns (16) + zero pad (48).
__global__ void pack_w_kernel(const float* __restrict__ w, int K,
                              __nv_bfloat16* __restrict__ Bq, int ldB,
                              float* __restrict__ scaleOut,
                              const float* __restrict__ u,
                              const float* __restrict__ gatep)
{
    int i = blockIdx.x;
    int t = threadIdx.x;  // 128 threads
    const float* wr = w + (size_t)i * K;
    double s = 0.0;
    for (int j = t; j < K; j += 128) s += fabs((double)wr[j]);
    for (int o = 16; o; o >>= 1) s += __shfl_down_sync(0xffffffffu, s, o);
    __shared__ double red[4];
    __shared__ float scsh;
    if ((t & 31) == 0) red[t >> 5] = s;
    __syncthreads();
    if (t == 0) {
        double tot = red[0] + red[1] + red[2] + red[3];
        float m = (float)(tot / K);
        scsh = fmaxf(m, 1e-5f);
        scaleOut[i] = scsh;
    }
    __syncthreads();
    float scale = scsh;
    __nv_bfloat16* br = Bq + (size_t)i * ldB;
    for (int j = t; j < K; j += 128) {
        float tern = rintf(wr[j] / scale);
        tern = fminf(fmaxf(tern, -1.f), 1.f);
        __nv_bfloat16 tb = __float2bfloat16(tern);
        br[j] = tb;
        br[K + j] = tb;
    }
    if (u != nullptr && t < 64) {
        float g = *gatep;
        float val = (t < 16) ? g * u[(size_t)i * 16 + t] / scale : 0.f;
        br[2 * K + t] = __float2bfloat16(val);
    }
}

// x -> bf16 hi/lo into A1 columns [0,1024) and [1024,2048)
__global__ void split_x_kernel(const float* __restrict__ x)
{
    size_t idx = (size_t)blockIdx.x * blockDim.x + threadIdx.x;
    if (idx >= (size_t)MTOK * DIMD) return;
    size_t m = idx >> 10;
    int k = (int)(idx & 1023);
    float v = x[idx];
    __nv_bfloat16 h = __float2bfloat16(v);
    g_A1[m * K1 + k] = h;
    g_A1[m * K1 + 1024 + k] = __float2bfloat16(v - __bfloat162float(h));
}

// W = fast_b @ v  (16 x 1024)
__global__ void compose_w_kernel(const float* __restrict__ fb, const float* __restrict__ v)
{
    int idx = blockIdx.x * blockDim.x + threadIdx.x;
    if (idx >= 16 * DIMD) return;
    int j = idx >> 10, d = idx & 1023;
    float s = 0.f;
#pragma unroll
    for (int r = 0; r < 16; r++) s += fb[j * 16 + r] * v[r * DIMD + d];
    g_W[idx] = s;
}

// t2[m,j] = dot(x[m,:], W[j,:]); write to A1 cols [2048,2064), zero pad [2064,2112)
// one block per token row; x row cached in smem, W stays L1-resident.
__global__ void adapter_kernel(const float* __restrict__ x)
{
    __shared__ float xs[1024];
    int m = blockIdx.x;
    int tid = threadIdx.x;  // 128
    const float* xr = x + (size_t)m * DIMD;
    for (int i = tid; i < 1024; i += 128) xs[i] = xr[i];
    __syncthreads();
    int j = tid >> 3, p = tid & 7;   // j: 0..15 adapter col, p: 0..7 stripe
    const float* wr = g_W + j * 1024 + p * 128;
    const float* xp = xs + p * 128;
    float s = 0.f;
#pragma unroll 8
    for (int i = 0; i < 128; i++) s += xp[i] * wr[i];
#pragma unroll
    for (int o = 4; o; o >>= 1) s += __shfl_down_sync(0xffffffffu, s, o);
    __nv_bfloat16* row = g_A1 + (size_t)m * K1 + 2048;
    if (p == 0) row[j] = __float2bfloat16(s);
    if (tid < 48) row[16 + tid] = __float2bfloat16(0.f);
}

// ============================================================================
// GEMM: C[128,128] tile, bf16 HMMA (mma.sync m16n8k16), 3-stage cp.async pipe.
// A:[M,K] row-major bf16, B:[N,K] row-major bf16 (C = A @ B^T).
// EPI==1: h = scale_n*acc; r=relu(h); rr=r*r; write [bf16(rr)|bf16(rr-hi)] to g_R
// EPI==2: out = scale_n*acc (f32)
// ============================================================================
#define BM 128
#define BN 128
#define BK 64
#define NSTAGE 3
#define STAGEB 32768            // A 16KB + B 16KB
#define GEMM_SMEM (NSTAGE * STAGEB)

template <int EPI>
__global__ void __launch_bounds__(256, 1)
gemm_kernel(const __nv_bfloat16* __restrict__ A, const __nv_bfloat16* __restrict__ B,
            const float* __restrict__ scale, void* __restrict__ out,
            int ldA, int kChunks, int nTiles)
{
    extern __shared__ char smem_raw[];
    __shared__ float s_scale[BN];
    const uint32_t DATA = smem_to_u32(smem_raw);
    const int tid = (int)threadIdx.x;
    const int lane = tid & 31;
    const int wid = tid >> 5;
    const int wm = wid >> 2;          // 0..1 : 64-row slice of M
    const int wn = wid & 3;           // 0..3 : 32-col slice of N
    const int tile_m = (int)blockIdx.x / nTiles;
    const int tile_n = (int)blockIdx.x % nTiles;

    const char* Abase = (const char*)(A + (size_t)tile_m * BM * ldA);
    const char* Bbase = (const char*)(B + (size_t)tile_n * BN * ldA);
    const size_t ldb = (size_t)ldA * 2;

    // precomputed load pattern: 1024 16B-chunks per 16KB tile, 4 per thread
    const int lrow = tid >> 1;              // used via u below
    (void)lrow;

    auto load_stage = [&](int s, int j) {
        uint32_t base = DATA + s * STAGEB;
        const char* Ag = Abase + (size_t)j * (BK * 2);
        const char* Bg = Bbase + (size_t)j * (BK * 2);
#pragma unroll
        for (int i = 0; i < 4; i++) {
            int u = i * 256 + tid;          // 0..1023
            int r = u >> 3, c = u & 7;
            cp_async16(base + SW128(r * 128 + c * 16), Ag + (size_t)r * ldb + c * 16);
        }
#pragma unroll
        for (int i = 0; i < 4; i++) {
            int u = i * 256 + tid;
            int r = u >> 3, c = u & 7;
            cp_async16(base + 16384 + SW128(r * 128 + c * 16), Bg + (size_t)r * ldb + c * 16);
        }
        cp_commit();
    };

    float acc[16][4];
#pragma unroll
    for (int i = 0; i < 16; i++)
#pragma unroll
        for (int q = 0; q < 4; q++) acc[i][q] = 0.f;

    // prologue: stages 0..NSTAGE-2
    for (int j = 0; j < NSTAGE - 1 && j < kChunks; j++) load_stage(j, j);

    const int lr = lane & 15, lc = lane >> 4;

    for (int k = 0; k < kChunks; k++) {
        cp_wait<NSTAGE - 2>();
        __syncthreads();
        // prefetch chunk k+NSTAGE-1 into slot freed at the barrier above
        if (k + NSTAGE - 1 < kChunks)
            load_stage((k + NSTAGE - 1) % NSTAGE, k + NSTAGE - 1);
        else
            cp_commit();

        uint32_t sA = DATA + (k % NSTAGE) * STAGEB;
        uint32_t sB = sA + 16384;
#pragma unroll
        for (int ks = 0; ks < 4; ks++) {
            uint32_t afr[4][4], bfr[2][4];
            uint32_t bcol = ks * 32 + lc * 16;
#pragma unroll
            for (int im = 0; im < 4; im++) {
                int row = wm * 64 + im * 16 + lr;
                ldm_x4(sA + SW128((uint32_t)row * 128 + bcol), afr[im]);
            }
#pragma unroll
            for (int in2 = 0; in2 < 2; in2++) {
                int row = wn * 32 + in2 * 16 + lr;
                ldm_x4(sB + SW128((uint32_t)row * 128 + bcol), bfr[in2]);
            }
#pragma unroll
            for (int im = 0; im < 4; im++)
#pragma unroll
                for (int g = 0; g < 4; g++)
                    mma16816(acc[im * 4 + g], afr[im], bfr[g >> 1][g & 1], bfr[g >> 1][(g & 1) + 2]);
        }
    }

    // ---- epilogue ----
    if (tid < BN) s_scale[tid] = scale[tile_n * BN + tid];
    __syncthreads();

#pragma unroll
    for (int im = 0; im < 4; im++) {
#pragma unroll
        for (int g = 0; g < 4; g++) {
            const float* c = acc[im * 4 + g];
            int ncol = wn * 32 + g * 8 + (lane & 3) * 2;
            int row0 = tile_m * BM + wm * 64 + im * 16 + (lane >> 2);
            float s0 = s_scale[ncol], s1 = s_scale[ncol + 1];
            if (EPI == 1) {
#pragma unroll
                for (int half = 0; half < 2; half++) {
                    int row = row0 + half * 8;
                    float h0 = c[half * 2 + 0] * s0;
                    float h1 = c[half * 2 + 1] * s1;
                    float r0 = fmaxf(h0, 0.f), r1 = fmaxf(h1, 0.f);
                    float rr0 = r0 * r0, rr1 = r1 * r1;
                    __nv_bfloat16 h0b = __float2bfloat16(rr0);
                    __nv_bfloat16 h1b = __float2bfloat16(rr1);
                    __nv_bfloat162 hp, lp;
                    hp.x = h0b; hp.y = h1b;
                    lp.x = __float2bfloat16(rr0 - __bfloat162float(h0b));
                    lp.y = __float2bfloat16(rr1 - __bfloat162float(h1b));
                    __nv_bfloat16* orow = g_R + (size_t)row * K2 + tile_n * BN + ncol;
                    *(__nv_bfloat162*)orow = hp;
                    *(__nv_bfloat162*)(orow + HID) = lp;
                }
            } else {
#pragma unroll
                for (int half = 0; half < 2; half++) {
                    int row = row0 + half * 8;
                    float2 v;
                    v.x = c[half * 2 + 0] * s0;
                    v.y = c[half * 2 + 1] * s1;
                    float* orow = (float*)out + (size_t)row * DIMD + tile_n * BN + ncol;
                    *(float2*)orow = v;
                }
            }
        }
    }
}

// ============================================================================
// launch
// ============================================================================
extern "C" void kernel_launch(void* const* d_in, const int* in_sizes, int n_in,
                              void* d_out, int out_size)
{
    const float* x      = (const float*)d_in[0];
    const float* fast_b = (const float*)d_in[1];
    const float* w_fc   = (const float*)d_in[2];
    const float* w_proj = (const float*)d_in[3];
    const float* u      = (const float*)d_in[4];
    const float* v      = (const float*)d_in[5];
    const float* gate   = (const float*)d_in[6];

    void *pA1, *pB1, *pR, *pB2, *pSfc, *pSpj;
    cudaGetSymbolAddress(&pA1, g_A1);
    cudaGetSymbolAddress(&pB1, g_B1);
    cudaGetSymbolAddress(&pR,  g_R);
    cudaGetSymbolAddress(&pB2, g_B2);
    cudaGetSymbolAddress(&pSfc, g_scale_fc);
    cudaGetSymbolAddress(&pSpj, g_scale_pj);

    cudaFuncSetAttribute(gemm_kernel<1>, cudaFuncAttributeMaxDynamicSharedMemorySize, GEMM_SMEM);
    cudaFuncSetAttribute(gemm_kernel<2>, cudaFuncAttributeMaxDynamicSharedMemorySize, GEMM_SMEM);

    // prep
    pack_w_kernel<<<HID, 128>>>(w_fc, DIMD, (__nv_bfloat16*)pB1, K1, (float*)pSfc, u, gate);
    pack_w_kernel<<<DIMD, 128>>>(w_proj, HID, (__nv_bfloat16*)pB2, K2, (float*)pSpj, nullptr, nullptr);
    split_x_kernel<<<(MTOK * DIMD + 255) / 256, 256>>>(x);
    compose_w_kernel<<<(16 * DIMD + 255) / 256, 256>>>(fast_b, v);
    adapter_kernel<<<MTOK, 128>>>(x);

    // GEMM1: [16384 x 4096] = A1[16384 x 2112] @ B1[4096 x 2112]^T  (+ relu^2 split)
    gemm_kernel<1><<<(MTOK / BM) * (HID / BN), 256, GEMM_SMEM>>>(
        (const __nv_bfloat16*)pA1, (const __nv_bfloat16*)pB1,
        (const float*)pSfc, pR, K1, K1 / BK, HID / BN);

    // GEMM2: out[16384 x 1024] = R[16384 x 8192] @ B2[1024 x 8192]^T
    gemm_kernel<2><<<(MTOK / BM) * (DIMD / BN), 256, GEMM_SMEM>>>(
        (const __nv_bfloat16*)pR, (const __nv_bfloat16*)pB2,
        (const float*)pSpj, d_out, K2, K2 / BK, DIMD / BN);
}

// round 4
// speedup vs baseline: 1.4360x; 1.4360x over previous
#include <cuda_runtime.h>
#include <cuda_fp16.h>
#include <cstdint>
#include <cstddef>

// ---------------- problem dims (fixed for this problem) ----------------
#define DIMD 1024
#define HID  4096
#define MTOK 16384            // 4*4096 tokens
#define K1   1088             // 1024 + 16 adapter + 48 pad
#define K2   4096

// ---------------- device scratch (no cudaMalloc allowed) ----------------
__device__ __align__(1024) __half g_A1[(size_t)MTOK * K1];  // [x | t2 | 0]
__device__ __align__(1024) __half g_B1[(size_t)HID  * K1];  // [tern | g*u/s | 0]
__device__ __align__(1024) __half g_R [(size_t)MTOK * K2];  // rr
__device__ __align__(1024) __half g_B2[(size_t)DIMD * K2];  // tern
__device__ float g_scale_fc[HID];
__device__ float g_scale_pj[DIMD];
__device__ float g_W[16 * DIMD];   // fast_b @ v

// ---------------- helpers ----------------
__device__ __forceinline__ uint32_t smem_to_u32(const void* p) {
    uint32_t a;
    asm("{ .reg .u64 t; cvta.to.shared.u64 t, %1; cvt.u32.u64 %0, t; }" : "=r"(a) : "l"(p));
    return a;
}
#define SW128(o) ((o) ^ (((o) >> 3) & 0x70))

__device__ __forceinline__ void cp_async16(uint32_t s, const void* g) {
    asm volatile("cp.async.cg.shared.global [%0], [%1], 16;" :: "r"(s), "l"(g) : "memory");
}
__device__ __forceinline__ void cp_commit() {
    asm volatile("cp.async.commit_group;" ::: "memory");
}
template <int N>
__device__ __forceinline__ void cp_wait() {
    asm volatile("cp.async.wait_group %0;" :: "n"(N) : "memory");
}

__device__ __forceinline__ void ldm_x4(uint32_t addr, uint32_t* r) {
    asm volatile("ldmatrix.sync.aligned.m8n8.x4.shared.b16 {%0,%1,%2,%3}, [%4];"
        : "=r"(r[0]), "=r"(r[1]), "=r"(r[2]), "=r"(r[3]) : "r"(addr));
}
__device__ __forceinline__ void mma16816(float* c, const uint32_t* a, uint32_t b0, uint32_t b1) {
    asm volatile("mma.sync.aligned.m16n8k16.row.col.f32.f16.f16.f32 "
        "{%0,%1,%2,%3}, {%4,%5,%6,%7}, {%8,%9}, {%0,%1,%2,%3};"
        : "+f"(c[0]), "+f"(c[1]), "+f"(c[2]), "+f"(c[3])
        : "r"(a[0]), "r"(a[1]), "r"(a[2]), "r"(a[3]), "r"(b0), "r"(b1));
}

// ============================================================================
// prep kernels
// ============================================================================

// per-output-row abs-mean scale -> ternary pack (fp16, exact).
// For w_fc also append gate*u/scale columns (16) + zero pad (48).
__global__ void pack_w_kernel(const float* __restrict__ w, int K,
                              __half* __restrict__ Bq, int ldB,
                              float* __restrict__ scaleOut,
                              const float* __restrict__ u,
                              const float* __restrict__ gatep)
{
    int i = blockIdx.x;
    int t = threadIdx.x;  // 128 threads
    const float* wr = w + (size_t)i * K;
    double s = 0.0;
    for (int j = t; j < K; j += 128) s += fabs((double)wr[j]);
    for (int o = 16; o; o >>= 1) s += __shfl_down_sync(0xffffffffu, s, o);
    __shared__ double red[4];
    __shared__ float scsh;
    if ((t & 31) == 0) red[t >> 5] = s;
    __syncthreads();
    if (t == 0) {
        double tot = red[0] + red[1] + red[2] + red[3];
        float m = (float)(tot / K);
        scsh = fmaxf(m, 1e-5f);
        scaleOut[i] = scsh;
    }
    __syncthreads();
    float scale = scsh;
    __half* br = Bq + (size_t)i * ldB;
    for (int j = t; j < K; j += 128) {
        float tern = rintf(wr[j] / scale);
        tern = fminf(fmaxf(tern, -1.f), 1.f);
        br[j] = __float2half(tern);
    }
    if (u != nullptr && t < 64) {
        float g = *gatep;
        float val = (t < 16) ? g * u[(size_t)i * 16 + t] / scale : 0.f;
        br[K + t] = __float2half(val);
    }
}

// x -> fp16 into A1 columns [0,1024)
__global__ void cvt_x_kernel(const float* __restrict__ x)
{
    size_t idx = (size_t)blockIdx.x * blockDim.x + threadIdx.x;
    if (idx >= (size_t)MTOK * DIMD) return;
    size_t m = idx >> 10;
    int k = (int)(idx & 1023);
    g_A1[m * K1 + k] = __float2half(x[idx]);
}

// W = fast_b @ v  (16 x 1024)
__global__ void compose_w_kernel(const float* __restrict__ fb, const float* __restrict__ v)
{
    int idx = blockIdx.x * blockDim.x + threadIdx.x;
    if (idx >= 16 * DIMD) return;
    int j = idx >> 10, d = idx & 1023;
    float s = 0.f;
#pragma unroll
    for (int r = 0; r < 16; r++) s += fb[j * 16 + r] * v[r * DIMD + d];
    g_W[idx] = s;
}

// t2[m,j] = dot(x[m,:], W[j,:]); write to A1 cols [1024,1040), zero pad [1040,1088)
__global__ void adapter_kernel(const float* __restrict__ x)
{
    __shared__ float xs[1024];
    int m = blockIdx.x;
    int tid = threadIdx.x;  // 128
    const float* xr = x + (size_t)m * DIMD;
    for (int i = tid; i < 1024; i += 128) xs[i] = xr[i];
    __syncthreads();
    int j = tid >> 3, p = tid & 7;   // j: 0..15 adapter col, p: 0..7 stripe
    const float* wr = g_W + j * 1024 + p * 128;
    const float* xp = xs + p * 128;
    float s = 0.f;
#pragma unroll 8
    for (int i = 0; i < 128; i++) s += xp[i] * wr[i];
#pragma unroll
    for (int o = 4; o; o >>= 1) s += __shfl_down_sync(0xffffffffu, s, o);
    __half* row = g_A1 + (size_t)m * K1 + 1024;
    if (p == 0) row[j] = __float2half(s);
    if (tid < 48) row[16 + tid] = __float2half(0.f);
}

// ============================================================================
// GEMM: C[128,128] tile, fp16 HMMA (mma.sync m16n8k16, f32 acc),
// 4-stage cp.async pipe + register double-buffered fragments.
// A:[M,K] row-major fp16, B:[N,K] row-major fp16 (C = A @ B^T).
// EPI==1: h = scale_n*acc; r=relu(h); rr=r*r; write fp16(rr) to g_R
// EPI==2: out = scale_n*acc (f32)
// ============================================================================
#define BM 128
#define BN 128
#define BK 64
#define NSTAGE 4
#define STAGEB 32768            // A 16KB + B 16KB
#define GEMM_SMEM (NSTAGE * STAGEB)

template <int EPI>
__global__ void __launch_bounds__(256, 1)
gemm_kernel(const __half* __restrict__ A, const __half* __restrict__ B,
            const float* __restrict__ scale, void* __restrict__ out,
            int ldA, int kChunks, int nTiles)
{
    extern __shared__ char smem_raw[];
    __shared__ float s_scale[BN];
    const uint32_t DATA = smem_to_u32(smem_raw);
    const int tid = (int)threadIdx.x;
    const int lane = tid & 31;
    const int wid = tid >> 5;
    const int wm = wid >> 2;          // 0..1 : 64-row slice of M
    const int wn = wid & 3;           // 0..3 : 32-col slice of N
    const int tile_m = (int)blockIdx.x / nTiles;
    const int tile_n = (int)blockIdx.x % nTiles;

    const char* Abase = (const char*)(A + (size_t)tile_m * BM * ldA);
    const char* Bbase = (const char*)(B + (size_t)tile_n * BN * ldA);
    const size_t ldb = (size_t)ldA * 2;

    auto load_stage = [&](int s, int j) {
        uint32_t base = DATA + s * STAGEB;
        const char* Ag = Abase + (size_t)j * (BK * 2);
        const char* Bg = Bbase + (size_t)j * (BK * 2);
#pragma unroll
        for (int i = 0; i < 4; i++) {
            int u = i * 256 + tid;          // 0..1023
            int r = u >> 3, c = u & 7;
            cp_async16(base + SW128(r * 128 + c * 16), Ag + (size_t)r * ldb + c * 16);
        }
#pragma unroll
        for (int i = 0; i < 4; i++) {
            int u = i * 256 + tid;
            int r = u >> 3, c = u & 7;
            cp_async16(base + 16384 + SW128(r * 128 + c * 16), Bg + (size_t)r * ldb + c * 16);
        }
        cp_commit();
    };

    float acc[16][4];
#pragma unroll
    for (int i = 0; i < 16; i++)
#pragma unroll
        for (int q = 0; q < 4; q++) acc[i][q] = 0.f;

    // prologue: stages 0..NSTAGE-2
    for (int j = 0; j < NSTAGE - 1 && j < kChunks; j++) load_stage(j, j);

    const int lr = lane & 15, lc = lane >> 4;

    uint32_t afr[2][4][4], bfr[2][2][4];

    auto load_frags = [&](uint32_t sA, uint32_t sB, int ks, int buf) {
        uint32_t bcol = (uint32_t)(ks * 32 + lc * 16);
#pragma unroll
        for (int im = 0; im < 4; im++) {
            int row = wm * 64 + im * 16 + lr;
            ldm_x4(sA + SW128((uint32_t)row * 128 + bcol), afr[buf][im]);
        }
#pragma unroll
        for (int in2 = 0; in2 < 2; in2++) {
            int row = wn * 32 + in2 * 16 + lr;
            ldm_x4(sB + SW128((uint32_t)row * 128 + bcol), bfr[buf][in2]);
        }
    };

    for (int k = 0; k < kChunks; k++) {
        cp_wait<NSTAGE - 2>();
        __syncthreads();
        // prefetch chunk k+NSTAGE-1 into the slot freed at the barrier above
        if (k + NSTAGE - 1 < kChunks)
            load_stage((k + NSTAGE - 1) % NSTAGE, k + NSTAGE - 1);
        else
            cp_commit();

        uint32_t sA = DATA + (k % NSTAGE) * STAGEB;
        uint32_t sB = sA + 16384;

        load_frags(sA, sB, 0, 0);
#pragma unroll
        for (int ks = 0; ks < 4; ks++) {
            int cur = ks & 1;
            if (ks < 3) load_frags(sA, sB, ks + 1, cur ^ 1);
#pragma unroll
            for (int im = 0; im < 4; im++)
#pragma unroll
                for (int g = 0; g < 4; g++)
                    mma16816(acc[im * 4 + g], afr[cur][im],
                             bfr[cur][g >> 1][g & 1], bfr[cur][g >> 1][(g & 1) + 2]);
        }
    }

    // ---- epilogue ----
    if (tid < BN) s_scale[tid] = scale[tile_n * BN + tid];
    __syncthreads();

#pragma unroll
    for (int im = 0; im < 4; im++) {
#pragma unroll
        for (int g = 0; g < 4; g++) {
            const float* c = acc[im * 4 + g];
            int ncol = wn * 32 + g * 8 + (lane & 3) * 2;
            int row0 = tile_m * BM + wm * 64 + im * 16 + (lane >> 2);
            float s0 = s_scale[ncol], s1 = s_scale[ncol + 1];
            if (EPI == 1) {
#pragma unroll
                for (int half = 0; half < 2; half++) {
                    int row = row0 + half * 8;
                    float h0 = c[half * 2 + 0] * s0;
                    float h1 = c[half * 2 + 1] * s1;
                    float r0 = fmaxf(h0, 0.f), r1 = fmaxf(h1, 0.f);
                    __half2 hp;
                    hp.x = __float2half(r0 * r0);
                    hp.y = __float2half(r1 * r1);
                    __half* orow = g_R + (size_t)row * K2 + tile_n * BN + ncol;
                    *(__half2*)orow = hp;
                }
            } else {
#pragma unroll
                for (int half = 0; half < 2; half++) {
                    int row = row0 + half * 8;
                    float2 v;
                    v.x = c[half * 2 + 0] * s0;
                    v.y = c[half * 2 + 1] * s1;
                    float* orow = (float*)out + (size_t)row * DIMD + tile_n * BN + ncol;
                    *(float2*)orow = v;
                }
            }
        }
    }
}

// ============================================================================
// launch
// ============================================================================
extern "C" void kernel_launch(void* const* d_in, const int* in_sizes, int n_in,
                              void* d_out, int out_size)
{
    const float* x      = (const float*)d_in[0];
    const float* fast_b = (const float*)d_in[1];
    const float* w_fc   = (const float*)d_in[2];
    const float* w_proj = (const float*)d_in[3];
    const float* u      = (const float*)d_in[4];
    const float* v      = (const float*)d_in[5];
    const float* gate   = (const float*)d_in[6];

    void *pA1, *pB1, *pR, *pB2, *pSfc, *pSpj;
    cudaGetSymbolAddress(&pA1, g_A1);
    cudaGetSymbolAddress(&pB1, g_B1);
    cudaGetSymbolAddress(&pR,  g_R);
    cudaGetSymbolAddress(&pB2, g_B2);
    cudaGetSymbolAddress(&pSfc, g_scale_fc);
    cudaGetSymbolAddress(&pSpj, g_scale_pj);

    cudaFuncSetAttribute(gemm_kernel<1>, cudaFuncAttributeMaxDynamicSharedMemorySize, GEMM_SMEM);
    cudaFuncSetAttribute(gemm_kernel<2>, cudaFuncAttributeMaxDynamicSharedMemorySize, GEMM_SMEM);

    // prep
    pack_w_kernel<<<HID, 128>>>(w_fc, DIMD, (__half*)pB1, K1, (float*)pSfc, u, gate);
    pack_w_kernel<<<DIMD, 128>>>(w_proj, HID, (__half*)pB2, K2, (float*)pSpj, nullptr, nullptr);
    cvt_x_kernel<<<(MTOK * DIMD + 255) / 256, 256>>>(x);
    compose_w_kernel<<<(16 * DIMD + 255) / 256, 256>>>(fast_b, v);
    adapter_kernel<<<MTOK, 128>>>(x);

    // GEMM1: [16384 x 4096] = A1[16384 x 1088] @ B1[4096 x 1088]^T  (+ relu^2)
    gemm_kernel<1><<<(MTOK / BM) * (HID / BN), 256, GEMM_SMEM>>>(
        (const __half*)pA1, (const __half*)pB1,
        (const float*)pSfc, pR, K1, K1 / BK, HID / BN);

    // GEMM2: out[16384 x 1024] = R[16384 x 4096] @ B2[1024 x 4096]^T
    gemm_kernel<2><<<(MTOK / BM) * (DIMD / BN), 256, GEMM_SMEM>>>(
        (const __half*)pR, (const __half*)pB2,
        (const float*)pSpj, d_out, K2, K2 / BK, DIMD / BN);
}

// round 5
// speedup vs baseline: 1.4916x; 1.0387x over previous
#include <cuda_runtime.h>
#include <cuda_fp16.h>
#include <cstdint>
#include <cstddef>

// ---------------- problem dims (fixed for this problem) ----------------
#define DIMD 1024
#define HID  4096
#define MTOK 16384            // 4*4096 tokens
#define KC1  17               // GEMM1 k-chunks of 64: 1024 + (16 adapter + 48 pad)
#define KC2  64               // GEMM2 k-chunks of 64: 4096
#define TILEB 16384           // one 128x64 fp16 tile, SW128-swizzled

// Chunk-major tile layouts: buf[tileIdx][kchunk][128 rows][128B swizzled row]
// ---------------- device scratch (no cudaMalloc allowed) ----------------
__device__ __align__(1024) __half g_A1[(size_t)(MTOK / 128) * KC1 * TILEB / 2];
__device__ __align__(1024) __half g_B1[(size_t)(HID  / 128) * KC1 * TILEB / 2];
__device__ __align__(1024) __half g_R [(size_t)(MTOK / 128) * KC2 * TILEB / 2];
__device__ __align__(1024) __half g_B2[(size_t)(DIMD / 128) * KC2 * TILEB / 2];
__device__ float g_scale_fc[HID];
__device__ float g_scale_pj[DIMD];
__device__ float g_W[16 * DIMD];   // fast_b @ v

// ---------------- helpers ----------------
__device__ __forceinline__ uint32_t smem_to_u32(const void* p) {
    uint32_t a;
    asm("{ .reg .u64 t; cvta.to.shared.u64 t, %1; cvt.u32.u64 %0, t; }" : "=r"(a) : "l"(p));
    return a;
}
#define SW128(o) ((o) ^ (((o) >> 3) & 0x70))

#define MBARRIER_INIT(mbar, count) \
    asm volatile("mbarrier.init.shared.b64 [%0], %1;" :: "r"((uint32_t)(mbar)), "r"((uint32_t)(count)) : "memory")
#define MBARRIER_EXPECT_TX(mbar, tx) \
    asm volatile("mbarrier.arrive.expect_tx.shared.b64 _, [%0], %1;" :: "r"((uint32_t)(mbar)), "r"((uint32_t)(tx)) : "memory")
#define MBARRIER_ARRIVE(mbar) \
    asm volatile("mbarrier.arrive.shared.b64 _, [%0];" :: "r"((uint32_t)(mbar)) : "memory")

#define MBARRIER_WAIT_PARITY(mbar, par) do { \
    uint32_t _m = (uint32_t)(mbar); uint32_t _p = (uint32_t)(par); uint32_t _d; \
    asm volatile("{\n\t.reg .pred p;\n\t" \
        "mbarrier.try_wait.parity.acquire.cta.shared::cta.b64 p, [%1], %2;\n\t" \
        "selp.b32 %0, 1, 0, p;\n\t}" : "=r"(_d) : "r"(_m), "r"(_p) : "memory"); \
    if (!_d) { \
        asm volatile("{\n\t.reg .pred P1;\n\t" \
            "WL_%=:\n\t" \
            "mbarrier.try_wait.parity.acquire.cta.shared::cta.b64 P1, [%0], %1, 0x989680;\n\t" \
            "@P1 bra.uni WD_%=;\n\tbra.uni WL_%=;\n\tWD_%=:\n\t}" \
            :: "r"(_m), "r"(_p) : "memory"); \
    } \
} while (0)

// bulk async copy GMEM -> SMEM with mbarrier complete_tx (base sm_90 ISA)
__device__ __forceinline__ void bulk_g2s(uint32_t dst, const void* src, uint32_t bytes, uint32_t mbar) {
    asm volatile("cp.async.bulk.shared::cluster.global.mbarrier::complete_tx::bytes [%0], [%1], %2, [%3];"
        :: "r"(dst), "l"(src), "r"(bytes), "r"(mbar) : "memory");
}

__device__ __forceinline__ void ldm_x4(uint32_t addr, uint32_t* r) {
    asm volatile("ldmatrix.sync.aligned.m8n8.x4.shared.b16 {%0,%1,%2,%3}, [%4];"
        : "=r"(r[0]), "=r"(r[1]), "=r"(r[2]), "=r"(r[3]) : "r"(addr));
}
__device__ __forceinline__ void mma16816(float* c, const uint32_t* a, uint32_t b0, uint32_t b1) {
    asm volatile("mma.sync.aligned.m16n8k16.row.col.f32.f16.f16.f32 "
        "{%0,%1,%2,%3}, {%4,%5,%6,%7}, {%8,%9}, {%0,%1,%2,%3};"
        : "+f"(c[0]), "+f"(c[1]), "+f"(c[2]), "+f"(c[3])
        : "r"(a[0]), "r"(a[1]), "r"(a[2]), "r"(a[3]), "r"(b0), "r"(b1));
}

// chunk-major swizzled address (element granularity, returns byte offset)
__device__ __forceinline__ size_t cm_off(int tile, int kc, int nchunks, int row, int col /*fp16 col 0..63*/) {
    return (size_t)(tile * nchunks + kc) * TILEB + SW128((uint32_t)(row * 128 + col * 2));
}

// ============================================================================
// prep kernels (write chunk-major swizzled layouts directly)
// ============================================================================

// per-output-row abs-mean scale -> ternary pack (fp16, exact).
// For w_fc also append gate*u/scale columns (16) + zero pad (48) in chunk Kc-1.
__global__ void pack_w_kernel(const float* __restrict__ w, int K, int Kc,
                              __half* __restrict__ Bq,
                              float* __restrict__ scaleOut,
                              const float* __restrict__ u,
                              const float* __restrict__ gatep)
{
    int i = blockIdx.x;
    int t = threadIdx.x;  // 128 threads
    const float* wr = w + (size_t)i * K;
    double s = 0.0;
    for (int j = t; j < K; j += 128) s += fabs((double)wr[j]);
    for (int o = 16; o; o >>= 1) s += __shfl_down_sync(0xffffffffu, s, o);
    __shared__ double red[4];
    __shared__ float scsh;
    if ((t & 31) == 0) red[t >> 5] = s;
    __syncthreads();
    if (t == 0) {
        double tot = red[0] + red[1] + red[2] + red[3];
        float m = (float)(tot / K);
        scsh = fmaxf(m, 1e-5f);
        scaleOut[i] = scsh;
    }
    __syncthreads();
    float scale = scsh;
    char* base = (char*)Bq;
    int tile = i >> 7, row = i & 127;
    for (int j = t; j < K; j += 128) {
        float tern = rintf(wr[j] / scale);
        tern = fminf(fmaxf(tern, -1.f), 1.f);
        *(__half*)(base + cm_off(tile, j >> 6, Kc, row, j & 63)) = __float2half(tern);
    }
    if (u != nullptr && t < 64) {
        float g = *gatep;
        float val = (t < 16) ? g * u[(size_t)i * 16 + t] / scale : 0.f;
        *(__half*)(base + cm_off(tile, Kc - 1, Kc, row, t)) = __float2half(val);
    }
}

// x -> fp16 chunk-major A1 (chunks 0..15)
__global__ void cvt_x_kernel(const float* __restrict__ x)
{
    size_t idx = (size_t)blockIdx.x * blockDim.x + threadIdx.x;   // pairs
    if (idx >= (size_t)MTOK * DIMD / 2) return;
    size_t m = idx / 512;
    int k = ((int)(idx % 512)) * 2;
    const float2 v = *(const float2*)(x + m * DIMD + k);
    __half2 h;
    h.x = __float2half(v.x);
    h.y = __float2half(v.y);
    *(__half2*)((char*)g_A1 + cm_off((int)(m >> 7), k >> 6, KC1, (int)(m & 127), k & 63)) = h;
}

// W = fast_b @ v  (16 x 1024)
__global__ void compose_w_kernel(const float* __restrict__ fb, const float* __restrict__ v)
{
    int idx = blockIdx.x * blockDim.x + threadIdx.x;
    if (idx >= 16 * DIMD) return;
    int j = idx >> 10, d = idx & 1023;
    float s = 0.f;
#pragma unroll
    for (int r = 0; r < 16; r++) s += fb[j * 16 + r] * v[r * DIMD + d];
    g_W[idx] = s;
}

// t2[m,j] = dot(x[m,:], W[j,:]); write A1 chunk 16: cols 0..15, zero pad 16..63
__global__ void adapter_kernel(const float* __restrict__ x)
{
    __shared__ float xs[1024];
    int m = blockIdx.x;
    int tid = threadIdx.x;  // 128
    const float* xr = x + (size_t)m * DIMD;
    for (int i = tid; i < 1024; i += 128) xs[i] = xr[i];
    __syncthreads();
    int j = tid >> 3, p = tid & 7;
    const float* wr = g_W + j * 1024 + p * 128;
    const float* xp = xs + p * 128;
    float s = 0.f;
#pragma unroll 8
    for (int i = 0; i < 128; i++) s += xp[i] * wr[i];
#pragma unroll
    for (int o = 4; o; o >>= 1) s += __shfl_down_sync(0xffffffffu, s, o);
    int tile = m >> 7, row = m & 127;
    if (p == 0)
        *(__half*)((char*)g_A1 + cm_off(tile, KC1 - 1, KC1, row, j)) = __float2half(s);
    if (tid < 48)
        *(__half*)((char*)g_A1 + cm_off(tile, KC1 - 1, KC1, row, 16 + tid)) = __float2half(0.f);
}

// ============================================================================
// GEMM: C[128,128] tile, fp16 HMMA, cp.async.bulk (2 per chunk, single issuer)
// + mbarrier full/empty ring, register double-buffered fragments.
// A,B chunk-major swizzled tiles (C = A @ B^T semantics on original matrices).
// EPI==1: h = scale_n*acc; r=relu(h); rr=r*r; write fp16(rr) chunk-major to g_R
// EPI==2: out = scale_n*acc (f32) row-major
// ============================================================================
#define BM 128
#define BN 128
#define NSTAGE 6
#define STAGEB 32768            // A 16KB + B 16KB
#define GEMM_SMEM (NSTAGE * STAGEB)

template <int EPI>
__global__ void __launch_bounds__(256, 1)
gemm_kernel(const __half* __restrict__ A, const __half* __restrict__ B,
            const float* __restrict__ scale, void* __restrict__ out,
            int kChunks, int nTiles)
{
    extern __shared__ char smem_raw[];
    __shared__ __align__(8) uint64_t mbar_store[2 * NSTAGE];
    __shared__ float s_scale[BN];
    const uint32_t DATA = smem_to_u32(smem_raw);
    const uint32_t FULL = smem_to_u32(mbar_store);
    const uint32_t EMPTY = FULL + 8 * NSTAGE;
    const int tid = (int)threadIdx.x;
    const int lane = tid & 31;
    const int wid = tid >> 5;
    const int wm = wid >> 2;          // 0..1 : 64-row slice of M
    const int wn = wid & 3;           // 0..3 : 32-col slice of N
    const int tile_m = (int)blockIdx.x / nTiles;
    const int tile_n = (int)blockIdx.x % nTiles;

    if (tid == 0) {
#pragma unroll
        for (int s = 0; s < NSTAGE; s++) {
            MBARRIER_INIT(FULL + 8 * s, 1);
            MBARRIER_INIT(EMPTY + 8 * s, 256);
        }
    }
    __syncthreads();

    const char* Ab = (const char*)A + (size_t)tile_m * kChunks * TILEB;
    const char* Bb = (const char*)B + (size_t)tile_n * kChunks * TILEB;

    auto produce = [&](int j) {
        int s = j % NSTAGE;
        uint32_t dst = DATA + s * STAGEB;
        MBARRIER_EXPECT_TX(FULL + 8 * s, 2 * TILEB);
        bulk_g2s(dst,         Ab + (size_t)j * TILEB, TILEB, FULL + 8 * s);
        bulk_g2s(dst + TILEB, Bb + (size_t)j * TILEB, TILEB, FULL + 8 * s);
    };

    if (tid == 0) {
        int npre = kChunks < NSTAGE ? kChunks : NSTAGE;
        for (int j = 0; j < npre; j++) produce(j);
    }

    float acc[16][4];
#pragma unroll
    for (int i = 0; i < 16; i++)
#pragma unroll
        for (int q = 0; q < 4; q++) acc[i][q] = 0.f;

    const int lr = lane & 15, lc = lane >> 4;
    uint32_t afr[2][4][4], bfr[2][2][4];

    auto load_frags = [&](uint32_t sA, uint32_t sB, int ks, int buf) {
        uint32_t bcol = (uint32_t)(ks * 32 + lc * 16);
#pragma unroll
        for (int im = 0; im < 4; im++) {
            int row = wm * 64 + im * 16 + lr;
            ldm_x4(sA + SW128((uint32_t)row * 128 + bcol), afr[buf][im]);
        }
#pragma unroll
        for (int in2 = 0; in2 < 2; in2++) {
            int row = wn * 32 + in2 * 16 + lr;
            ldm_x4(sB + SW128((uint32_t)row * 128 + bcol), bfr[buf][in2]);
        }
    };

    for (int k = 0; k < kChunks; k++) {
        int s = k % NSTAGE;
        int ph = (k / NSTAGE) & 1;
        MBARRIER_WAIT_PARITY(FULL + 8 * s, ph);

        uint32_t sA = DATA + s * STAGEB;
        uint32_t sB = sA + TILEB;

        load_frags(sA, sB, 0, 0);
#pragma unroll
        for (int ks = 0; ks < 4; ks++) {
            int cur = ks & 1;
            if (ks < 3) load_frags(sA, sB, ks + 1, cur ^ 1);
#pragma unroll
            for (int im = 0; im < 4; im++)
#pragma unroll
                for (int g = 0; g < 4; g++)
                    mma16816(acc[im * 4 + g], afr[cur][im],
                             bfr[cur][g >> 1][g & 1], bfr[cur][g >> 1][(g & 1) + 2]);
        }
        // release this stage (release semantics order our smem reads)
        MBARRIER_ARRIVE(EMPTY + 8 * s);
        if (tid == 0) {
            int j = k + NSTAGE;
            if (j < kChunks) {
                MBARRIER_WAIT_PARITY(EMPTY + 8 * s, ph);
                produce(j);
            }
        }
    }

    // ---- epilogue ----
    if (tid < BN) s_scale[tid] = scale[tile_n * BN + tid];
    __syncthreads();

#pragma unroll
    for (int im = 0; im < 4; im++) {
#pragma unroll
        for (int g = 0; g < 4; g++) {
            const float* c = acc[im * 4 + g];
            int ncol = wn * 32 + g * 8 + (lane & 3) * 2;
            int lrow0 = wm * 64 + im * 16 + (lane >> 2);
            float s0 = s_scale[ncol], s1 = s_scale[ncol + 1];
            if (EPI == 1) {
                int gcol = tile_n * BN + ncol;
                int kc = gcol >> 6, cc = gcol & 63;
#pragma unroll
                for (int half = 0; half < 2; half++) {
                    int lrow = lrow0 + half * 8;
                    float h0 = c[half * 2 + 0] * s0;
                    float h1 = c[half * 2 + 1] * s1;
                    float r0 = fmaxf(h0, 0.f), r1 = fmaxf(h1, 0.f);
                    __half2 hp;
                    hp.x = __float2half(r0 * r0);
                    hp.y = __float2half(r1 * r1);
                    *(__half2*)((char*)g_R + cm_off(tile_m, kc, KC2, lrow, cc)) = hp;
                }
            } else {
#pragma unroll
                for (int half = 0; half < 2; half++) {
                    int row = tile_m * BM + lrow0 + half * 8;
                    float2 v;
                    v.x = c[half * 2 + 0] * s0;
                    v.y = c[half * 2 + 1] * s1;
                    float* orow = (float*)out + (size_t)row * DIMD + tile_n * BN + ncol;
                    *(float2*)orow = v;
                }
            }
        }
    }
}

// ============================================================================
// launch
// ============================================================================
extern "C" void kernel_launch(void* const* d_in, const int* in_sizes, int n_in,
                              void* d_out, int out_size)
{
    const float* x      = (const float*)d_in[0];
    const float* fast_b = (const float*)d_in[1];
    const float* w_fc   = (const float*)d_in[2];
    const float* w_proj = (const float*)d_in[3];
    const float* u      = (const float*)d_in[4];
    const float* v      = (const float*)d_in[5];
    const float* gate   = (const float*)d_in[6];

    void *pA1, *pB1, *pR, *pB2, *pSfc, *pSpj;
    cudaGetSymbolAddress(&pA1, g_A1);
    cudaGetSymbolAddress(&pB1, g_B1);
    cudaGetSymbolAddress(&pR,  g_R);
    cudaGetSymbolAddress(&pB2, g_B2);
    cudaGetSymbolAddress(&pSfc, g_scale_fc);
    cudaGetSymbolAddress(&pSpj, g_scale_pj);

    cudaFuncSetAttribute(gemm_kernel<1>, cudaFuncAttributeMaxDynamicSharedMemorySize, GEMM_SMEM);
    cudaFuncSetAttribute(gemm_kernel<2>, cudaFuncAttributeMaxDynamicSharedMemorySize, GEMM_SMEM);

    // prep
    pack_w_kernel<<<HID, 128>>>(w_fc, DIMD, KC1, (__half*)pB1, (float*)pSfc, u, gate);
    pack_w_kernel<<<DIMD, 128>>>(w_proj, HID, KC2, (__half*)pB2, (float*)pSpj, nullptr, nullptr);
    cvt_x_kernel<<<(MTOK * DIMD / 2 + 255) / 256, 256>>>(x);
    compose_w_kernel<<<(16 * DIMD + 255) / 256, 256>>>(fast_b, v);
    adapter_kernel<<<MTOK, 128>>>(x);

    // GEMM1: [16384 x 4096] = A1 @ B1^T  (+ relu^2), K = 17*64
    gemm_kernel<1><<<(MTOK / BM) * (HID / BN), 256, GEMM_SMEM>>>(
        (const __half*)pA1, (const __half*)pB1,
        (const float*)pSfc, pR, KC1, HID / BN);

    // GEMM2: out[16384 x 1024] = R @ B2^T, K = 64*64
    gemm_kernel<2><<<(MTOK / BM) * (DIMD / BN), 256, GEMM_SMEM>>>(
        (const __half*)pR, (const __half*)pB2,
        (const float*)pSpj, d_out, KC2, DIMD / BN);
}